// round 11
// baseline (speedup 1.0000x reference)
#include <cuda_runtime.h>
#include <math.h>

// Problem constants
#define PB_N0 2048
#define PB_N1 32768
#define PB_N2 524288
#define PB_C  16
#define PB_D  128
#define PB_H  128
#define PB_ED 8

#define H2_STRIDE 132   // tile stride: A-fragment reads conflict-free (4g+tg)

// ---------------- scratch (device globals; no runtime allocation) ----------
__device__ float    g_pooled[(size_t)PB_N1 * PB_H];  // 16.8 MB (reused at level 0)
__device__ float    g_h1[(size_t)PB_N1 * PB_H];      // 16.8 MB
__device__ unsigned g_Wc[3 * PB_D * PB_H];           // tf32 bits: W_fe @ W_x[l][:128]
__device__ unsigned g_Whc[2 * PB_H * PB_H];          // tf32 bits: W_h levels 0,1
__device__ unsigned g_Wgc[2 * PB_H * PB_H];          // tf32 bits: W_g levels 0,1
__device__ float    g_bias[3 * PB_H];                // b_fe @ W_x[l][:128] + b_r[l]

// ---------------- tf32 / math helpers ---------------------------------------
__device__ __forceinline__ unsigned f2tf(float f) {
    unsigned r; asm("cvt.rna.tf32.f32 %0, %1;" : "=r"(r) : "f"(f)); return r;
}
__device__ __forceinline__ void mma8(float4& d, const unsigned a[4],
                                     unsigned b0, unsigned b1) {
    asm volatile(
        "mma.sync.aligned.m16n8k8.row.col.f32.tf32.tf32.f32 "
        "{%0,%1,%2,%3},{%4,%5,%6,%7},{%8,%9},{%0,%1,%2,%3};"
        : "+f"(d.x), "+f"(d.y), "+f"(d.z), "+f"(d.w)
        : "r"(a[0]), "r"(a[1]), "r"(a[2]), "r"(a[3]), "r"(b0), "r"(b1));
}
__device__ __forceinline__ float fast_tanh(float x) {
    float e = __expf(2.f * x);
    return 1.f - __fdividef(2.f, e + 1.f);
}

// ---------------- whole-tile preload: fp32 global -> tf32 smem (stride 132) -
__device__ __forceinline__ void loadTile(unsigned* dst, const float* src,
                                         size_t rowbase, int t) {
    #pragma unroll
    for (int u = 0; u < 16; ++u) {
        int f = t + u * 256; int r = f >> 5, c4 = (f & 31) * 4;
        float4 v = *(const float4*)(src + (rowbase + r) * 128 + c4);
        uint4 w;
        w.x = f2tf(v.x); w.y = f2tf(v.y); w.z = f2tf(v.z); w.w = f2tf(v.w);
        *(uint4*)(dst + r * H2_STRIDE + c4) = w;
    }
}

// one 16-K mma step; A from smem tile T (stride 132) at K offset kb,
// B fragments directly from GLOBAL weight matrix W [128 K x 128 N], tf32 bits.
// Per LDG.32: 4x32B sectors (coalesced within quads) = 1 L1 wavefront.
__device__ __forceinline__ void mma_chunk_g(float4 acc[4][4],
                                            const unsigned* T, int kb,
                                            const unsigned* __restrict__ W,
                                            int warpM, int warpN, int g, int tg) {
    #pragma unroll
    for (int ks = 0; ks < 2; ++ks) {
        int k0 = kb + ks * 8;
        unsigned a[4][4], b[4][2];
        #pragma unroll
        for (int j = 0; j < 4; ++j) {
            int col = warpN * 32 + j * 8 + g;
            b[j][0] = __ldg(W + (size_t)(k0 + tg) * 128 + col);
            b[j][1] = __ldg(W + (size_t)(k0 + tg + 4) * 128 + col);
        }
        #pragma unroll
        for (int i = 0; i < 4; ++i) {
            int rb = warpM * 64 + i * 16;
            a[i][0] = T[(rb + g) * H2_STRIDE + k0 + tg];
            a[i][1] = T[(rb + g + 8) * H2_STRIDE + k0 + tg];
            a[i][2] = T[(rb + g) * H2_STRIDE + k0 + tg + 4];
            a[i][3] = T[(rb + g + 8) * H2_STRIDE + k0 + tg + 4];
        }
        #pragma unroll
        for (int i = 0; i < 4; ++i)
            #pragma unroll
            for (int j = 0; j < 4; ++j) mma8(acc[i][j], a[i], b[j][0], b[j][1]);
    }
}

// ---------------- prep: Wc[l] = tf32(W_fe @ W_x[l][0:128,:]) ----------------
__global__ void prep_wc(const float* __restrict__ W_fe,
                        const float* __restrict__ W_x) {
    int l = blockIdx.x >> 7;
    int d = blockIdx.x & 127;
    int h = threadIdx.x;
    const float* wx = W_x + (size_t)l * 132 * 128;
    float acc = 0.f;
    #pragma unroll 8
    for (int k = 0; k < 128; ++k)
        acc += W_fe[d * 128 + k] * wx[k * 128 + h];
    g_Wc[((size_t)l * 128 + d) * 128 + h] = f2tf(acc);
}

__global__ void prep_bias(const float* __restrict__ b_fe,
                          const float* __restrict__ W_x,
                          const float* __restrict__ b_r) {
    int l = blockIdx.x;
    int h = threadIdx.x;
    const float* wx = W_x + (size_t)l * 132 * 128;
    float acc = b_r[l * 128 + h];
    #pragma unroll 8
    for (int d = 0; d < 128; ++d)
        acc += b_fe[d] * wx[d * 128 + h];
    g_bias[l * 128 + h] = acc;
}

__global__ void prep_cvt(const float* __restrict__ Wh,
                         const float* __restrict__ Wg) {
    int i = blockIdx.x * 256 + threadIdx.x;   // 0 .. 32767
    g_Whc[i] = f2tf(Wh[i]);
    g_Wgc[i] = f2tf(Wg[i]);
}

// ============================================================================
// fused_level: per block 128 child rows = 8 parents (warp w <-> parent w).
// X tile preloaded whole into h2s; B operands streamed from global (L1-hot).
// The entire K loop of each GEMM phase is barrier-free.
// ============================================================================
__global__ void __launch_bounds__(256, 2)
fused_level(const float* __restrict__ xin, const int* __restrict__ tvec,
            const float* __restrict__ tapg, const unsigned* __restrict__ Wc,
            const float* __restrict__ biasg,
            const float* __restrict__ hin,
            const float* __restrict__ Ag, const float* __restrict__ Eg,
            const float* __restrict__ Weg,
            const unsigned* __restrict__ Wg, const float* __restrict__ bgg,
            float* __restrict__ pooled)
{
    extern __shared__ unsigned char smraw[];
    unsigned* h2s = (unsigned*)smraw;                       // [128][132]
    float* taps   = (float*)(h2s + 128 * H2_STRIDE);        // [4][128]
    float* bgs    = taps + 4 * 128;                         // [128]
    float* biass  = bgs + 128;                              // [128]
    int*   ts     = (int*)(biass + 128);                    // [128]

    const int t = threadIdx.x;
    const int lane = t & 31, wid = t >> 5;
    const int warpM = wid >> 2, warpN = wid & 3;
    const int g = lane >> 2, tg = lane & 3;
    const size_t rowbase = (size_t)blockIdx.x * 128;

    if (t < 128) bgs[t] = bgg[t];

    float4 acc[4][4];
    float gg[2][2][2];   // [c8][k8][k4] gate values for this lane's parent

    if (xin) {
        if (t < 128) { biass[t] = biasg[t]; ts[t] = tvec[rowbase + t]; }
        taps[t] = tapg[t]; taps[t + 256] = tapg[t + 256];

        // preload full X tile into h2s (tf32 bits)
        loadTile(h2s, xin, rowbase, t);

        #pragma unroll
        for (int i = 0; i < 4; ++i)
            #pragma unroll
            for (int j = 0; j < 4; ++j) acc[i][j] = make_float4(0.f, 0.f, 0.f, 0.f);

        __syncthreads();   // X tile visible

        #pragma unroll
        for (int it = 0; it < 8; ++it)
            mma_chunk_g(acc, h2s, it * 16, Wc, warpM, warpN, g, tg);

        // gates (register-resident; no h2s access)
        {
            const size_t ebase = (size_t)blockIdx.x * 2048 + wid * 256;
            float we0 = Weg[0], we1 = Weg[1], we2 = Weg[2], we3 = Weg[3];
            float we4 = Weg[4], we5 = Weg[5], we6 = Weg[6], we7 = Weg[7];
            #pragma unroll
            for (int c8 = 0; c8 < 2; ++c8)
                #pragma unroll
                for (int k8 = 0; k8 < 2; ++k8)
                    #pragma unroll
                    for (int k4 = 0; k4 < 2; ++k4) {
                        int c = g + 8 * c8, k = tg + 4 * k4 + 8 * k8;
                        const float* e = Eg + (ebase + c * 16 + k) * 8;
                        float4 e0 = *(const float4*)(e);
                        float4 e1 = *(const float4*)(e + 4);
                        float s = e0.x * we0 + e0.y * we1 + e0.z * we2 + e0.w * we3
                                + e1.x * we4 + e1.y * we5 + e1.z * we6 + e1.w * we7;
                        gg[c8][k8][k4] = Ag[ebase + c * 16 + k] / (1.f + __expf(-s));
                    }
        }

        __syncthreads();   // all X fragment reads done before overwriting h2s

        // epilogue: fast tanh -> h2s (tf32 bits)
        #pragma unroll
        for (int i = 0; i < 4; ++i) {
            int r0 = warpM * 64 + i * 16 + g, r1 = r0 + 8;
            const float* tap0 = taps + ts[r0] * 128;
            const float* tap1 = taps + ts[r1] * 128;
            #pragma unroll
            for (int j = 0; j < 4; ++j) {
                int c0 = warpN * 32 + j * 8 + tg * 2;
                h2s[r0 * H2_STRIDE + c0]     = f2tf(fast_tanh(acc[i][j].x + biass[c0]     + tap0[c0]));
                h2s[r0 * H2_STRIDE + c0 + 1] = f2tf(fast_tanh(acc[i][j].y + biass[c0 + 1] + tap0[c0 + 1]));
                h2s[r1 * H2_STRIDE + c0]     = f2tf(fast_tanh(acc[i][j].z + biass[c0]     + tap1[c0]));
                h2s[r1 * H2_STRIDE + c0 + 1] = f2tf(fast_tanh(acc[i][j].w + biass[c0 + 1] + tap1[c0 + 1]));
            }
        }
    } else {
        // load child hidden tile from global (cvt + STS.128)
        loadTile(h2s, hin, rowbase, t);
        {
            const size_t ebase = (size_t)blockIdx.x * 2048 + wid * 256;
            float we0 = Weg[0], we1 = Weg[1], we2 = Weg[2], we3 = Weg[3];
            float we4 = Weg[4], we5 = Weg[5], we6 = Weg[6], we7 = Weg[7];
            #pragma unroll
            for (int c8 = 0; c8 < 2; ++c8)
                #pragma unroll
                for (int k8 = 0; k8 < 2; ++k8)
                    #pragma unroll
                    for (int k4 = 0; k4 < 2; ++k4) {
                        int c = g + 8 * c8, k = tg + 4 * k4 + 8 * k8;
                        const float* e = Eg + (ebase + c * 16 + k) * 8;
                        float4 e0 = *(const float4*)(e);
                        float4 e1 = *(const float4*)(e + 4);
                        float s = e0.x * we0 + e0.y * we1 + e0.z * we2 + e0.w * we3
                                + e1.x * we4 + e1.y * we5 + e1.z * we6 + e1.w * we7;
                        gg[c8][k8][k4] = Ag[ebase + c * 16 + k] / (1.f + __expf(-s));
                    }
        }
    }
    __syncthreads();   // h2s (child hidden) complete

    // Phase C: per-parent mix M_p = G_p @ child_h_p  (warp wid = parent)
    {
        float4 macc[16];
        #pragma unroll
        for (int j = 0; j < 16; ++j) macc[j] = make_float4(0.f, 0.f, 0.f, 0.f);
        int p = wid;
        #pragma unroll
        for (int ks = 0; ks < 2; ++ks) {
            unsigned a[4];
            a[0] = f2tf(gg[0][ks][0]);
            a[1] = f2tf(gg[1][ks][0]);
            a[2] = f2tf(gg[0][ks][1]);
            a[3] = f2tf(gg[1][ks][1]);
            #pragma unroll
            for (int j = 0; j < 16; ++j) {
                unsigned b0 = h2s[(p * 16 + ks * 8 + tg) * H2_STRIDE + j * 8 + g];
                unsigned b1 = h2s[(p * 16 + ks * 8 + tg + 4) * H2_STRIDE + j * 8 + g];
                mma8(macc[j], a, b0, b1);
            }
        }
        __syncwarp();
        #pragma unroll
        for (int j = 0; j < 16; ++j) {
            int c0 = j * 8 + tg * 2;
            h2s[(p * 16 + g) * H2_STRIDE + c0]         = f2tf(macc[j].x);
            h2s[(p * 16 + g) * H2_STRIDE + c0 + 1]     = f2tf(macc[j].y);
            h2s[(p * 16 + g + 8) * H2_STRIDE + c0]     = f2tf(macc[j].z);
            h2s[(p * 16 + g + 8) * H2_STRIDE + c0 + 1] = f2tf(macc[j].w);
        }
    }
    __syncthreads();

    // Phase D: Hc = relu(M @ Wg + bg); maxpool over each parent's 16 rows
    #pragma unroll
    for (int i = 0; i < 4; ++i)
        #pragma unroll
        for (int j = 0; j < 4; ++j) acc[i][j] = make_float4(0.f, 0.f, 0.f, 0.f);

    #pragma unroll
    for (int it = 0; it < 8; ++it)
        mma_chunk_g(acc, h2s, it * 16, Wg, warpM, warpN, g, tg);

    // relu + 16-row maxpool (m-tile i == parent warpM*4+i exactly)
    #pragma unroll
    for (int i = 0; i < 4; ++i) {
        size_t parent = (size_t)blockIdx.x * 8 + warpM * 4 + i;
        #pragma unroll
        for (int j = 0; j < 4; ++j) {
            int c0 = warpN * 32 + j * 8 + tg * 2;
            float b0 = bgs[c0], b1 = bgs[c0 + 1];
            float v0 = fmaxf(fmaxf(acc[i][j].x + b0, acc[i][j].z + b0), 0.f);
            float v1 = fmaxf(fmaxf(acc[i][j].y + b1, acc[i][j].w + b1), 0.f);
            #pragma unroll
            for (int off = 16; off >= 4; off >>= 1) {
                v0 = fmaxf(v0, __shfl_xor_sync(0xffffffffu, v0, off));
                v1 = fmaxf(v1, __shfl_xor_sync(0xffffffffu, v1, off));
            }
            if (lane < 4)
                *(float2*)(pooled + parent * 128 + c0) = make_float2(v0, v1);
        }
    }
}

// ============================================================================
// gemm_tanh: out = tanh(A0 @ W0 + A1 @ W1 + bias + typerow[t]) , tf32 mma
// Per-segment whole-tile preload; B direct from global. Two barriers total.
// ============================================================================
__global__ void __launch_bounds__(256, 2)
gemm_tanh(const float* __restrict__ A0g, const unsigned* __restrict__ W0,
          const float* __restrict__ A1g, const unsigned* __restrict__ W1,
          const float* __restrict__ biasg, const float* __restrict__ tapg,
          const int* __restrict__ tvec, float* __restrict__ out)
{
    extern __shared__ unsigned char smraw[];
    unsigned* Xt  = (unsigned*)smraw;                       // [128][132]
    float* taps   = (float*)(Xt + 128 * H2_STRIDE);         // [4][128]
    float* biass  = taps + 4 * 128;                         // [128]
    int*   ts     = (int*)(biass + 128);                    // [128]

    const int t = threadIdx.x;
    const int lane = t & 31, wid = t >> 5;
    const int warpM = wid >> 2, warpN = wid & 3;
    const int g = lane >> 2, tg = lane & 3;
    const size_t rowbase = (size_t)blockIdx.x * 128;

    if (t < 128) { biass[t] = biasg[t]; ts[t] = tvec[rowbase + t]; }
    taps[t] = tapg[t]; taps[t + 256] = tapg[t + 256];

    const float* Aseg[2] = {A0g, A1g};
    const unsigned* Wseg[2] = {W0, W1};

    float4 acc[4][4];
    #pragma unroll
    for (int i = 0; i < 4; ++i)
        #pragma unroll
        for (int j = 0; j < 4; ++j) acc[i][j] = make_float4(0.f, 0.f, 0.f, 0.f);

    #pragma unroll
    for (int seg = 0; seg < 2; ++seg) {
        if (seg) __syncthreads();        // prior segment's tile reads done
        loadTile(Xt, Aseg[seg], rowbase, t);
        __syncthreads();                 // tile visible
        #pragma unroll
        for (int it = 0; it < 8; ++it)
            mma_chunk_g(acc, Xt, it * 16, Wseg[seg], warpM, warpN, g, tg);
    }

    #pragma unroll
    for (int i = 0; i < 4; ++i) {
        int r0 = warpM * 64 + i * 16 + g, r1 = r0 + 8;
        const float* tap0 = taps + ts[r0] * 128;
        const float* tap1 = taps + ts[r1] * 128;
        #pragma unroll
        for (int j = 0; j < 4; ++j) {
            int c0 = warpN * 32 + j * 8 + tg * 2;
            float o0 = fast_tanh(acc[i][j].x + biass[c0]     + tap0[c0]);
            float o1 = fast_tanh(acc[i][j].y + biass[c0 + 1] + tap0[c0 + 1]);
            float o2 = fast_tanh(acc[i][j].z + biass[c0]     + tap1[c0]);
            float o3 = fast_tanh(acc[i][j].w + biass[c0 + 1] + tap1[c0 + 1]);
            *(float2*)(out + (rowbase + r0) * 128 + c0) = make_float2(o0, o1);
            *(float2*)(out + (rowbase + r1) * 128 + c0) = make_float2(o2, o3);
        }
    }
}

// ---------------- launch -----------------------------------------------
extern "C" void kernel_launch(void* const* d_in, const int* in_sizes, int n_in,
                              void* d_out, int out_size) {
    const float* x0   = (const float*)d_in[0];
    const float* x1   = (const float*)d_in[1];
    const float* x2   = (const float*)d_in[2];
    const int*   t0   = (const int*)  d_in[3];
    const int*   t1   = (const int*)  d_in[4];
    const int*   t2   = (const int*)  d_in[5];
    const float* A0   = (const float*)d_in[6];
    const float* A1   = (const float*)d_in[7];
    const float* E0   = (const float*)d_in[8];
    const float* E1   = (const float*)d_in[9];
    const float* W_fe = (const float*)d_in[10];
    const float* b_fe = (const float*)d_in[11];
    const float* W_x  = (const float*)d_in[12];
    const float* W_h  = (const float*)d_in[13];
    const float* W_e  = (const float*)d_in[14];
    const float* W_g  = (const float*)d_in[15];
    const float* b_g  = (const float*)d_in[16];
    const float* b_r  = (const float*)d_in[17];

    float *pooled, *h1, *bias;
    unsigned *Wc, *Whc, *Wgc;
    cudaGetSymbolAddress((void**)&pooled, g_pooled);
    cudaGetSymbolAddress((void**)&h1,     g_h1);
    cudaGetSymbolAddress((void**)&Wc,     g_Wc);
    cudaGetSymbolAddress((void**)&Whc,    g_Whc);
    cudaGetSymbolAddress((void**)&Wgc,    g_Wgc);
    cudaGetSymbolAddress((void**)&bias,   g_bias);

    const int SMEM_FL = 128 * H2_STRIDE * 4
                      + (4 * 128 + 128 + 128 + 128) * 4;   // 70,656 B
    const int SMEM_GT = 128 * H2_STRIDE * 4
                      + (4 * 128 + 128 + 128) * 4;         // 70,144 B
    cudaFuncSetAttribute(fused_level, cudaFuncAttributeMaxDynamicSharedMemorySize, SMEM_FL);
    cudaFuncSetAttribute(gemm_tanh,   cudaFuncAttributeMaxDynamicSharedMemorySize, SMEM_GT);

    // fold W_fe/b_fe into per-level weights; pre-convert weights to tf32
    prep_wc<<<3 * 128, 128>>>(W_fe, W_x);
    prep_bias<<<3, 128>>>(b_fe, W_x, b_r);
    prep_cvt<<<128, 256>>>(W_h, W_g);

    // level 2 + level 1 GNN fused: x2 -> h2 (smem) -> gate/mix -> relu GEMM -> pooled1
    fused_level<<<PB_N2 / 128, 256, SMEM_FL>>>(
        x2, t2, W_x + 2 * 132 * 128 + 128 * 128, Wc + 2 * 128 * 128, bias + 2 * 128,
        nullptr, A1, E1, W_e + 8, Wgc + 128 * 128, b_g + 128, pooled);

    // h1 = tanh(x1 @ Wc1 + pooled1 @ W_h1 + bias1 + typerow)
    gemm_tanh<<<PB_N1 / 128, 256, SMEM_GT>>>(
        x1, Wc + 128 * 128, pooled, Whc + 128 * 128,
        bias + 128, W_x + 132 * 128 + 128 * 128, t1, h1);

    // level 0 GNN fused (child hidden loaded from h1)
    fused_level<<<PB_N1 / 128, 256, SMEM_FL>>>(
        nullptr, nullptr, nullptr, nullptr, nullptr,
        h1, A0, E0, W_e, Wgc, b_g, pooled);

    // roots: h0 -> d_out
    gemm_tanh<<<PB_N0 / 128, 256, SMEM_GT>>>(
        x0, Wc, pooled, Whc,
        bias, W_x + 128 * 128, t0, (float*)d_out);
}

// round 12
// speedup vs baseline: 1.2709x; 1.2709x over previous
#include <cuda_runtime.h>
#include <math.h>

// Problem constants
#define PB_N0 2048
#define PB_N1 32768
#define PB_N2 524288
#define PB_C  16
#define PB_D  128
#define PB_H  128
#define PB_ED 8

#define H2_STRIDE 132   // tile stride: A-fragment reads conflict-free (4g+tg)
#define WK_STRIDE 136   // weight-chunk stride: B-fragment reads conflict-free (8tg+g)

// ---------------- scratch (device globals; no runtime allocation) ----------
__device__ float    g_pooled[(size_t)PB_N1 * PB_H];  // 16.8 MB (reused at level 0)
__device__ float    g_h1[(size_t)PB_N1 * PB_H];      // 16.8 MB
__device__ unsigned g_Wc[3 * PB_D * PB_H];           // tf32 bits: W_fe @ W_x[l][:128]
__device__ unsigned g_Whc[2 * PB_H * PB_H];          // tf32 bits: W_h levels 0,1
__device__ unsigned g_Wgc[2 * PB_H * PB_H];          // tf32 bits: W_g levels 0,1
__device__ float    g_bias[3 * PB_H];                // b_fe @ W_x[l][:128] + b_r[l]

// ---------------- tf32 / math helpers ---------------------------------------
__device__ __forceinline__ unsigned f2tf(float f) {
    unsigned r; asm("cvt.rna.tf32.f32 %0, %1;" : "=r"(r) : "f"(f)); return r;
}
__device__ __forceinline__ void mma8(float4& d, const unsigned a[4],
                                     unsigned b0, unsigned b1) {
    asm volatile(
        "mma.sync.aligned.m16n8k8.row.col.f32.tf32.tf32.f32 "
        "{%0,%1,%2,%3},{%4,%5,%6,%7},{%8,%9},{%0,%1,%2,%3};"
        : "+f"(d.x), "+f"(d.y), "+f"(d.z), "+f"(d.w)
        : "r"(a[0]), "r"(a[1]), "r"(a[2]), "r"(a[3]), "r"(b0), "r"(b1));
}
__device__ __forceinline__ float fast_tanh(float x) {
    float e = __expf(2.f * x);
    return 1.f - __fdividef(2.f, e + 1.f);
}

// ---------------- whole-tile preload: fp32 global -> tf32 smem (stride 132) -
__device__ __forceinline__ void loadTile(unsigned* dst, const float* src,
                                         size_t rowbase, int t) {
    #pragma unroll
    for (int u = 0; u < 16; ++u) {
        int f = t + u * 256; int r = f >> 5, c4 = (f & 31) * 4;
        float4 v = *(const float4*)(src + (rowbase + r) * 128 + c4);
        uint4 w;
        w.x = f2tf(v.x); w.y = f2tf(v.y); w.z = f2tf(v.z); w.w = f2tf(v.w);
        *(uint4*)(dst + r * H2_STRIDE + c4) = w;
    }
}

// ---------------- W chunk staging via cp.async (tf32 bits, 16B) -------------
__device__ __forceinline__ void cpWc(unsigned* Wb, const unsigned* W, int kb, int t) {
    int f = t, r = f >> 5, c4 = (f & 31) * 4;
    unsigned d0 = (unsigned)__cvta_generic_to_shared(Wb + r * WK_STRIDE + c4);
    asm volatile("cp.async.cg.shared.global [%0], [%1], 16;"
                 :: "r"(d0), "l"(W + (size_t)(kb + r) * 128 + c4) : "memory");
    f = t + 256; r = f >> 5; c4 = (f & 31) * 4;
    unsigned d1 = (unsigned)__cvta_generic_to_shared(Wb + r * WK_STRIDE + c4);
    asm volatile("cp.async.cg.shared.global [%0], [%1], 16;"
                 :: "r"(d1), "l"(W + (size_t)(kb + r) * 128 + c4) : "memory");
}
#define CP_COMMIT() asm volatile("cp.async.commit_group;" ::: "memory")
#define CP_WAIT0()  asm volatile("cp.async.wait_group 0;" ::: "memory")

// one 16-K mma step; A from full tile T (stride 132) at K offset kb
__device__ __forceinline__ void mma_chunk_t(float4 acc[4][4],
                                            const unsigned* T, int kb,
                                            const unsigned* Wb,
                                            int warpM, int warpN, int g, int tg) {
    #pragma unroll
    for (int ks = 0; ks < 2; ++ks) {
        int k0 = kb + ks * 8;
        unsigned a[4][4], b[4][2];
        #pragma unroll
        for (int i = 0; i < 4; ++i) {
            int rb = warpM * 64 + i * 16;
            a[i][0] = T[(rb + g) * H2_STRIDE + k0 + tg];
            a[i][1] = T[(rb + g + 8) * H2_STRIDE + k0 + tg];
            a[i][2] = T[(rb + g) * H2_STRIDE + k0 + tg + 4];
            a[i][3] = T[(rb + g + 8) * H2_STRIDE + k0 + tg + 4];
        }
        #pragma unroll
        for (int j = 0; j < 4; ++j) {
            int col = warpN * 32 + j * 8 + g;
            b[j][0] = Wb[(ks * 8 + tg) * WK_STRIDE + col];
            b[j][1] = Wb[(ks * 8 + tg + 4) * WK_STRIDE + col];
        }
        #pragma unroll
        for (int i = 0; i < 4; ++i)
            #pragma unroll
            for (int j = 0; j < 4; ++j) mma8(acc[i][j], a[i], b[j][0], b[j][1]);
    }
}

// ---------------- prep: Wc[l] = tf32(W_fe @ W_x[l][0:128,:]) ----------------
__global__ void prep_wc(const float* __restrict__ W_fe,
                        const float* __restrict__ W_x) {
    int l = blockIdx.x >> 7;
    int d = blockIdx.x & 127;
    int h = threadIdx.x;
    const float* wx = W_x + (size_t)l * 132 * 128;
    float acc = 0.f;
    #pragma unroll 8
    for (int k = 0; k < 128; ++k)
        acc += W_fe[d * 128 + k] * wx[k * 128 + h];
    g_Wc[((size_t)l * 128 + d) * 128 + h] = f2tf(acc);
}

__global__ void prep_bias(const float* __restrict__ b_fe,
                          const float* __restrict__ W_x,
                          const float* __restrict__ b_r) {
    int l = blockIdx.x;
    int h = threadIdx.x;
    const float* wx = W_x + (size_t)l * 132 * 128;
    float acc = b_r[l * 128 + h];
    #pragma unroll 8
    for (int d = 0; d < 128; ++d)
        acc += b_fe[d] * wx[d * 128 + h];
    g_bias[l * 128 + h] = acc;
}

__global__ void prep_cvt(const float* __restrict__ Wh,
                         const float* __restrict__ Wg) {
    int i = blockIdx.x * 256 + threadIdx.x;   // 0 .. 32767
    g_Whc[i] = f2tf(Wh[i]);
    g_Wgc[i] = f2tf(Wg[i]);
}

// ============================================================================
// fused_level: per block 128 child rows = 8 parents (warp w <-> parent w).
// X tile preloaded whole into h2s; W chunks staged via cp.async double-buffer.
// ============================================================================
__global__ void __launch_bounds__(256, 2)
fused_level(const float* __restrict__ xin, const int* __restrict__ tvec,
            const float* __restrict__ tapg, const unsigned* __restrict__ Wc,
            const float* __restrict__ biasg,
            const float* __restrict__ hin,
            const float* __restrict__ Ag, const float* __restrict__ Eg,
            const float* __restrict__ Weg,
            const unsigned* __restrict__ Wg, const float* __restrict__ bgg,
            float* __restrict__ pooled)
{
    extern __shared__ unsigned char smraw[];
    unsigned* h2s = (unsigned*)smraw;                       // [128][132]
    unsigned* Wks = h2s + 128 * H2_STRIDE;                  // [2][16][136]
    float* taps   = (float*)(Wks + 2 * 16 * WK_STRIDE);     // [4][128]
    float* bgs    = taps + 4 * 128;                         // [128]
    float* biass  = bgs + 128;                              // [128]
    int*   ts     = (int*)(biass + 128);                    // [128]

    const int t = threadIdx.x;
    const int lane = t & 31, wid = t >> 5;
    const int warpM = wid >> 2, warpN = wid & 3;
    const int g = lane >> 2, tg = lane & 3;
    const size_t rowbase = (size_t)blockIdx.x * 128;

    if (t < 128) bgs[t] = bgg[t];

    float4 acc[4][4];
    float gg[2][2][2];   // [c8][k8][k4] gate values for this lane's parent

    if (xin) {
        if (t < 128) { biass[t] = biasg[t]; ts[t] = tvec[rowbase + t]; }
        taps[t] = tapg[t]; taps[t + 256] = tapg[t + 256];

        // preload full X tile into h2s (tf32 bits)
        loadTile(h2s, xin, rowbase, t);

        #pragma unroll
        for (int i = 0; i < 4; ++i)
            #pragma unroll
            for (int j = 0; j < 4; ++j) acc[i][j] = make_float4(0.f, 0.f, 0.f, 0.f);

        cpWc(Wks, Wc, 0, t); CP_COMMIT();
        #pragma unroll
        for (int it = 0; it < 8; ++it) {
            CP_WAIT0();
            __syncthreads();            // chunk it visible; tile visible at it==0
            if (it < 7) { cpWc(Wks + ((it + 1) & 1) * 16 * WK_STRIDE, Wc, (it + 1) * 16, t); CP_COMMIT(); }
            mma_chunk_t(acc, h2s, it * 16, Wks + (it & 1) * 16 * WK_STRIDE,
                        warpM, warpN, g, tg);
        }

        // gates (register-resident; no h2s access)
        {
            const size_t ebase = (size_t)blockIdx.x * 2048 + wid * 256;
            float we0 = Weg[0], we1 = Weg[1], we2 = Weg[2], we3 = Weg[3];
            float we4 = Weg[4], we5 = Weg[5], we6 = Weg[6], we7 = Weg[7];
            #pragma unroll
            for (int c8 = 0; c8 < 2; ++c8)
                #pragma unroll
                for (int k8 = 0; k8 < 2; ++k8)
                    #pragma unroll
                    for (int k4 = 0; k4 < 2; ++k4) {
                        int c = g + 8 * c8, k = tg + 4 * k4 + 8 * k8;
                        const float* e = Eg + (ebase + c * 16 + k) * 8;
                        float4 e0 = *(const float4*)(e);
                        float4 e1 = *(const float4*)(e + 4);
                        float s = e0.x * we0 + e0.y * we1 + e0.z * we2 + e0.w * we3
                                + e1.x * we4 + e1.y * we5 + e1.z * we6 + e1.w * we7;
                        gg[c8][k8][k4] = Ag[ebase + c * 16 + k] / (1.f + __expf(-s));
                    }
        }

        __syncthreads();   // all X fragment reads done before overwriting h2s

        // epilogue: fast tanh -> h2s (tf32 bits, packed STS.64)
        #pragma unroll
        for (int i = 0; i < 4; ++i) {
            int r0 = warpM * 64 + i * 16 + g, r1 = r0 + 8;
            const float* tap0 = taps + ts[r0] * 128;
            const float* tap1 = taps + ts[r1] * 128;
            #pragma unroll
            for (int j = 0; j < 4; ++j) {
                int c0 = warpN * 32 + j * 8 + tg * 2;
                uint2 w0, w1;
                w0.x = f2tf(fast_tanh(acc[i][j].x + biass[c0]     + tap0[c0]));
                w0.y = f2tf(fast_tanh(acc[i][j].y + biass[c0 + 1] + tap0[c0 + 1]));
                w1.x = f2tf(fast_tanh(acc[i][j].z + biass[c0]     + tap1[c0]));
                w1.y = f2tf(fast_tanh(acc[i][j].w + biass[c0 + 1] + tap1[c0 + 1]));
                *(uint2*)(h2s + r0 * H2_STRIDE + c0) = w0;
                *(uint2*)(h2s + r1 * H2_STRIDE + c0) = w1;
            }
        }
    } else {
        // load child hidden tile from global (cvt + STS.128)
        loadTile(h2s, hin, rowbase, t);
        {
            const size_t ebase = (size_t)blockIdx.x * 2048 + wid * 256;
            float we0 = Weg[0], we1 = Weg[1], we2 = Weg[2], we3 = Weg[3];
            float we4 = Weg[4], we5 = Weg[5], we6 = Weg[6], we7 = Weg[7];
            #pragma unroll
            for (int c8 = 0; c8 < 2; ++c8)
                #pragma unroll
                for (int k8 = 0; k8 < 2; ++k8)
                    #pragma unroll
                    for (int k4 = 0; k4 < 2; ++k4) {
                        int c = g + 8 * c8, k = tg + 4 * k4 + 8 * k8;
                        const float* e = Eg + (ebase + c * 16 + k) * 8;
                        float4 e0 = *(const float4*)(e);
                        float4 e1 = *(const float4*)(e + 4);
                        float s = e0.x * we0 + e0.y * we1 + e0.z * we2 + e0.w * we3
                                + e1.x * we4 + e1.y * we5 + e1.z * we6 + e1.w * we7;
                        gg[c8][k8][k4] = Ag[ebase + c * 16 + k] / (1.f + __expf(-s));
                    }
        }
    }
    __syncthreads();   // h2s (child hidden) complete

    // Phase C: per-parent mix M_p = G_p @ child_h_p  (warp wid = parent)
    {
        float4 macc[16];
        #pragma unroll
        for (int j = 0; j < 16; ++j) macc[j] = make_float4(0.f, 0.f, 0.f, 0.f);
        int p = wid;
        #pragma unroll
        for (int ks = 0; ks < 2; ++ks) {
            unsigned a[4];
            a[0] = f2tf(gg[0][ks][0]);
            a[1] = f2tf(gg[1][ks][0]);
            a[2] = f2tf(gg[0][ks][1]);
            a[3] = f2tf(gg[1][ks][1]);
            #pragma unroll
            for (int j = 0; j < 16; ++j) {
                unsigned b0 = h2s[(p * 16 + ks * 8 + tg) * H2_STRIDE + j * 8 + g];
                unsigned b1 = h2s[(p * 16 + ks * 8 + tg + 4) * H2_STRIDE + j * 8 + g];
                mma8(macc[j], a, b0, b1);
            }
        }
        __syncwarp();
        #pragma unroll
        for (int j = 0; j < 16; ++j) {
            int c0 = j * 8 + tg * 2;
            uint2 w0, w1;
            w0.x = f2tf(macc[j].x); w0.y = f2tf(macc[j].y);
            w1.x = f2tf(macc[j].z); w1.y = f2tf(macc[j].w);
            *(uint2*)(h2s + (p * 16 + g) * H2_STRIDE + c0)     = w0;
            *(uint2*)(h2s + (p * 16 + g + 8) * H2_STRIDE + c0) = w1;
        }
    }
    __syncthreads();

    // Phase D: Hc = relu(M @ Wg + bg); maxpool over each parent's 16 rows
    #pragma unroll
    for (int i = 0; i < 4; ++i)
        #pragma unroll
        for (int j = 0; j < 4; ++j) acc[i][j] = make_float4(0.f, 0.f, 0.f, 0.f);

    cpWc(Wks, Wg, 0, t); CP_COMMIT();
    #pragma unroll
    for (int it = 0; it < 8; ++it) {
        CP_WAIT0();
        __syncthreads();
        if (it < 7) { cpWc(Wks + ((it + 1) & 1) * 16 * WK_STRIDE, Wg, (it + 1) * 16, t); CP_COMMIT(); }
        mma_chunk_t(acc, h2s, it * 16, Wks + (it & 1) * 16 * WK_STRIDE,
                    warpM, warpN, g, tg);
    }

    // relu + 16-row maxpool (m-tile i == parent warpM*4+i exactly)
    #pragma unroll
    for (int i = 0; i < 4; ++i) {
        size_t parent = (size_t)blockIdx.x * 8 + warpM * 4 + i;
        #pragma unroll
        for (int j = 0; j < 4; ++j) {
            int c0 = warpN * 32 + j * 8 + tg * 2;
            float b0 = bgs[c0], b1 = bgs[c0 + 1];
            float v0 = fmaxf(fmaxf(acc[i][j].x + b0, acc[i][j].z + b0), 0.f);
            float v1 = fmaxf(fmaxf(acc[i][j].y + b1, acc[i][j].w + b1), 0.f);
            #pragma unroll
            for (int off = 16; off >= 4; off >>= 1) {
                v0 = fmaxf(v0, __shfl_xor_sync(0xffffffffu, v0, off));
                v1 = fmaxf(v1, __shfl_xor_sync(0xffffffffu, v1, off));
            }
            if (lane < 4)
                *(float2*)(pooled + parent * 128 + c0) = make_float2(v0, v1);
        }
    }
}

// ============================================================================
// gemm_tanh: out = tanh(A0 @ W0 + A1 @ W1 + bias + typerow[t]) , tf32 mma
// Per-segment whole-tile preload; W chunks via cp.async double-buffer.
// ============================================================================
__global__ void __launch_bounds__(256, 2)
gemm_tanh(const float* __restrict__ A0g, const unsigned* __restrict__ W0,
          const float* __restrict__ A1g, const unsigned* __restrict__ W1,
          const float* __restrict__ biasg, const float* __restrict__ tapg,
          const int* __restrict__ tvec, float* __restrict__ out)
{
    extern __shared__ unsigned char smraw[];
    unsigned* Xt  = (unsigned*)smraw;                       // [128][132]
    unsigned* Wks = Xt + 128 * H2_STRIDE;                   // [2][16][136]
    float* taps   = (float*)(Wks + 2 * 16 * WK_STRIDE);     // [4][128]
    float* biass  = taps + 4 * 128;                         // [128]
    int*   ts     = (int*)(biass + 128);                    // [128]

    const int t = threadIdx.x;
    const int lane = t & 31, wid = t >> 5;
    const int warpM = wid >> 2, warpN = wid & 3;
    const int g = lane >> 2, tg = lane & 3;
    const size_t rowbase = (size_t)blockIdx.x * 128;

    if (t < 128) { biass[t] = biasg[t]; ts[t] = tvec[rowbase + t]; }
    taps[t] = tapg[t]; taps[t + 256] = tapg[t + 256];

    const float* Aseg[2] = {A0g, A1g};
    const unsigned* Wseg[2] = {W0, W1};

    float4 acc[4][4];
    #pragma unroll
    for (int i = 0; i < 4; ++i)
        #pragma unroll
        for (int j = 0; j < 4; ++j) acc[i][j] = make_float4(0.f, 0.f, 0.f, 0.f);

    #pragma unroll
    for (int seg = 0; seg < 2; ++seg) {
        if (seg) __syncthreads();        // prior segment's tile reads done
        loadTile(Xt, Aseg[seg], rowbase, t);
        cpWc(Wks, Wseg[seg], 0, t); CP_COMMIT();
        #pragma unroll
        for (int it = 0; it < 8; ++it) {
            CP_WAIT0();
            __syncthreads();             // chunk + tile visible
            if (it < 7) { cpWc(Wks + ((it + 1) & 1) * 16 * WK_STRIDE, Wseg[seg], (it + 1) * 16, t); CP_COMMIT(); }
            mma_chunk_t(acc, Xt, it * 16, Wks + (it & 1) * 16 * WK_STRIDE,
                        warpM, warpN, g, tg);
        }
    }

    #pragma unroll
    for (int i = 0; i < 4; ++i) {
        int r0 = warpM * 64 + i * 16 + g, r1 = r0 + 8;
        const float* tap0 = taps + ts[r0] * 128;
        const float* tap1 = taps + ts[r1] * 128;
        #pragma unroll
        for (int j = 0; j < 4; ++j) {
            int c0 = warpN * 32 + j * 8 + tg * 2;
            float o0 = fast_tanh(acc[i][j].x + biass[c0]     + tap0[c0]);
            float o1 = fast_tanh(acc[i][j].y + biass[c0 + 1] + tap0[c0 + 1]);
            float o2 = fast_tanh(acc[i][j].z + biass[c0]     + tap1[c0]);
            float o3 = fast_tanh(acc[i][j].w + biass[c0 + 1] + tap1[c0 + 1]);
            *(float2*)(out + (rowbase + r0) * 128 + c0) = make_float2(o0, o1);
            *(float2*)(out + (rowbase + r1) * 128 + c0) = make_float2(o2, o3);
        }
    }
}

// ---------------- launch -----------------------------------------------
extern "C" void kernel_launch(void* const* d_in, const int* in_sizes, int n_in,
                              void* d_out, int out_size) {
    const float* x0   = (const float*)d_in[0];
    const float* x1   = (const float*)d_in[1];
    const float* x2   = (const float*)d_in[2];
    const int*   t0   = (const int*)  d_in[3];
    const int*   t1   = (const int*)  d_in[4];
    const int*   t2   = (const int*)  d_in[5];
    const float* A0   = (const float*)d_in[6];
    const float* A1   = (const float*)d_in[7];
    const float* E0   = (const float*)d_in[8];
    const float* E1   = (const float*)d_in[9];
    const float* W_fe = (const float*)d_in[10];
    const float* b_fe = (const float*)d_in[11];
    const float* W_x  = (const float*)d_in[12];
    const float* W_h  = (const float*)d_in[13];
    const float* W_e  = (const float*)d_in[14];
    const float* W_g  = (const float*)d_in[15];
    const float* b_g  = (const float*)d_in[16];
    const float* b_r  = (const float*)d_in[17];

    float *pooled, *h1, *bias;
    unsigned *Wc, *Whc, *Wgc;
    cudaGetSymbolAddress((void**)&pooled, g_pooled);
    cudaGetSymbolAddress((void**)&h1,     g_h1);
    cudaGetSymbolAddress((void**)&Wc,     g_Wc);
    cudaGetSymbolAddress((void**)&Whc,    g_Whc);
    cudaGetSymbolAddress((void**)&Wgc,    g_Wgc);
    cudaGetSymbolAddress((void**)&bias,   g_bias);

    const int SMEM_FL = (128 * H2_STRIDE + 2 * 16 * WK_STRIDE) * 4
                      + (4 * 128 + 128 + 128 + 128) * 4;   // 88,576 B
    const int SMEM_GT = (128 * H2_STRIDE + 2 * 16 * WK_STRIDE) * 4
                      + (4 * 128 + 128 + 128) * 4;         // 88,064 B
    cudaFuncSetAttribute(fused_level, cudaFuncAttributeMaxDynamicSharedMemorySize, SMEM_FL);
    cudaFuncSetAttribute(gemm_tanh,   cudaFuncAttributeMaxDynamicSharedMemorySize, SMEM_GT);

    // fold W_fe/b_fe into per-level weights; pre-convert weights to tf32
    prep_wc<<<3 * 128, 128>>>(W_fe, W_x);
    prep_bias<<<3, 128>>>(b_fe, W_x, b_r);
    prep_cvt<<<128, 256>>>(W_h, W_g);

    // level 2 + level 1 GNN fused: x2 -> h2 (smem) -> gate/mix -> relu GEMM -> pooled1
    fused_level<<<PB_N2 / 128, 256, SMEM_FL>>>(
        x2, t2, W_x + 2 * 132 * 128 + 128 * 128, Wc + 2 * 128 * 128, bias + 2 * 128,
        nullptr, A1, E1, W_e + 8, Wgc + 128 * 128, b_g + 128, pooled);

    // h1 = tanh(x1 @ Wc1 + pooled1 @ W_h1 + bias1 + typerow)
    gemm_tanh<<<PB_N1 / 128, 256, SMEM_GT>>>(
        x1, Wc + 128 * 128, pooled, Whc + 128 * 128,
        bias + 128, W_x + 132 * 128 + 128 * 128, t1, h1);

    // level 0 GNN fused (child hidden loaded from h1)
    fused_level<<<PB_N1 / 128, 256, SMEM_FL>>>(
        nullptr, nullptr, nullptr, nullptr, nullptr,
        h1, A0, E0, W_e, Wgc, b_g, pooled);

    // roots: h0 -> d_out
    gemm_tanh<<<PB_N0 / 128, 256, SMEM_GT>>>(
        x0, Wc, pooled, Whc,
        bias, W_x + 128 * 128, t0, (float*)d_out);
}

// round 13
// speedup vs baseline: 1.2985x; 1.0218x over previous
#include <cuda_runtime.h>
#include <math.h>

// Problem constants
#define PB_N0 2048
#define PB_N1 32768
#define PB_N2 524288
#define PB_C  16
#define PB_D  128
#define PB_H  128
#define PB_ED 8

#define H2_STRIDE 132   // tile stride: A-fragment LDSM conflict-free
#define WT_STRIDE 20    // transposed-W chunk stride [n][k]: B LDSM conflict-free
#define WT_CH (128 * WT_STRIDE)   // 2560 u32 per chunk buffer

// ---------------- scratch (device globals; no runtime allocation) ----------
__device__ float    g_pooled[(size_t)PB_N1 * PB_H];  // 16.8 MB (reused at level 0)
__device__ float    g_h1[(size_t)PB_N1 * PB_H];      // 16.8 MB
__device__ unsigned g_Wc[3 * PB_D * PB_H];           // tf32 bits, TRANSPOSED [n][k]
__device__ unsigned g_Whc[2 * PB_H * PB_H];          // tf32 bits, TRANSPOSED [n][k]
__device__ unsigned g_Wgc[2 * PB_H * PB_H];          // tf32 bits, TRANSPOSED [n][k]
__device__ float    g_bias[3 * PB_H];                // b_fe @ W_x[l][:128] + b_r[l]

// ---------------- tf32 / math helpers ---------------------------------------
__device__ __forceinline__ unsigned f2tf(float f) {
    unsigned r; asm("cvt.rna.tf32.f32 %0, %1;" : "=r"(r) : "f"(f)); return r;
}
__device__ __forceinline__ void mma8(float4& d, const unsigned a[4],
                                     unsigned b0, unsigned b1) {
    asm volatile(
        "mma.sync.aligned.m16n8k8.row.col.f32.tf32.tf32.f32 "
        "{%0,%1,%2,%3},{%4,%5,%6,%7},{%8,%9},{%0,%1,%2,%3};"
        : "+f"(d.x), "+f"(d.y), "+f"(d.z), "+f"(d.w)
        : "r"(a[0]), "r"(a[1]), "r"(a[2]), "r"(a[3]), "r"(b0), "r"(b1));
}
__device__ __forceinline__ void ldsm4(unsigned r[4], const unsigned* p) {
    unsigned addr = (unsigned)__cvta_generic_to_shared(p);
    asm volatile("ldmatrix.sync.aligned.m8n8.x4.shared.b16 {%0,%1,%2,%3}, [%4];"
                 : "=r"(r[0]), "=r"(r[1]), "=r"(r[2]), "=r"(r[3]) : "r"(addr));
}
__device__ __forceinline__ float fast_tanh(float x) {
    float e = __expf(2.f * x);
    return 1.f - __fdividef(2.f, e + 1.f);
}

// ---------------- whole-tile preload: fp32 global -> tf32 smem (stride 132) -
__device__ __forceinline__ void loadTile(unsigned* dst, const float* src,
                                         size_t rowbase, int t) {
    #pragma unroll
    for (int u = 0; u < 16; ++u) {
        int f = t + u * 256; int r = f >> 5, c4 = (f & 31) * 4;
        float4 v = *(const float4*)(src + (rowbase + r) * 128 + c4);
        uint4 w;
        w.x = f2tf(v.x); w.y = f2tf(v.y); w.z = f2tf(v.z); w.w = f2tf(v.w);
        *(uint4*)(dst + r * H2_STRIDE + c4) = w;
    }
}

// ---------------- W chunk staging via cp.async (transposed [n][k], 16B) -----
// W global: [128 n][128 k] tf32 bits; chunk dst: [128 n][WT_STRIDE] (16 k used)
__device__ __forceinline__ void cpWc(unsigned* Wb, const unsigned* W, int kb, int t) {
    int f = t, n = f >> 2, k4 = (f & 3) * 4;
    unsigned d0 = (unsigned)__cvta_generic_to_shared(Wb + n * WT_STRIDE + k4);
    asm volatile("cp.async.cg.shared.global [%0], [%1], 16;"
                 :: "r"(d0), "l"(W + (size_t)n * 128 + kb + k4) : "memory");
    f = t + 256; n = f >> 2; k4 = (f & 3) * 4;
    unsigned d1 = (unsigned)__cvta_generic_to_shared(Wb + n * WT_STRIDE + k4);
    asm volatile("cp.async.cg.shared.global [%0], [%1], 16;"
                 :: "r"(d1), "l"(W + (size_t)n * 128 + kb + k4) : "memory");
}
#define CP_COMMIT() asm volatile("cp.async.commit_group;" ::: "memory")
#define CP_WAIT0()  asm volatile("cp.async.wait_group 0;" ::: "memory")

// one 16-K mma step: A-frags via 4x LDSM.x4 from tile T (abs k), B-frags via
// 2x LDSM.x4 from transposed W chunk (local k).
__device__ __forceinline__ void mma_chunk_t(float4 acc[4][4],
                                            const unsigned* T, int kb,
                                            const unsigned* Wb,
                                            int warpM, int warpN, int lane) {
    const int aRow = warpM * 64 + (lane & 7) + ((lane >> 3) & 1) * 8;
    const int aK   = ((lane >> 4) & 1) * 4;
    const int bN   = warpN * 32 + (lane & 7) + ((lane >> 4) & 1) * 8;
    const int bK   = ((lane >> 3) & 1) * 4;
    #pragma unroll
    for (int ks = 0; ks < 2; ++ks) {
        int k0 = kb + ks * 8;
        unsigned a[4][4], b0[4], b1[4];
        ldsm4(b0, Wb + bN * WT_STRIDE + ks * 8 + bK);          // b[0][01], b[1][01]
        ldsm4(b1, Wb + (bN + 16) * WT_STRIDE + ks * 8 + bK);   // b[2][01], b[3][01]
        #pragma unroll
        for (int i = 0; i < 4; ++i)
            ldsm4(a[i], T + (aRow + i * 16) * H2_STRIDE + k0 + aK);
        #pragma unroll
        for (int i = 0; i < 4; ++i) {
            mma8(acc[i][0], a[i], b0[0], b0[1]);
            mma8(acc[i][1], a[i], b0[2], b0[3]);
            mma8(acc[i][2], a[i], b1[0], b1[1]);
            mma8(acc[i][3], a[i], b1[2], b1[3]);
        }
    }
}

// ---------------- prep: Wc[l] = tf32(W_fe @ W_x[l][0:128,:]) TRANSPOSED ------
__global__ void prep_wc(const float* __restrict__ W_fe,
                        const float* __restrict__ W_x) {
    int l = blockIdx.x >> 7;
    int d = blockIdx.x & 127;    // K index
    int h = threadIdx.x;         // N index
    const float* wx = W_x + (size_t)l * 132 * 128;
    float acc = 0.f;
    #pragma unroll 8
    for (int k = 0; k < 128; ++k)
        acc += W_fe[d * 128 + k] * wx[k * 128 + h];
    g_Wc[((size_t)l * 128 + h) * 128 + d] = f2tf(acc);   // [n][k]
}

__global__ void prep_bias(const float* __restrict__ b_fe,
                          const float* __restrict__ W_x,
                          const float* __restrict__ b_r) {
    int l = blockIdx.x;
    int h = threadIdx.x;
    const float* wx = W_x + (size_t)l * 132 * 128;
    float acc = b_r[l * 128 + h];
    #pragma unroll 8
    for (int d = 0; d < 128; ++d)
        acc += b_fe[d] * wx[d * 128 + h];
    g_bias[l * 128 + h] = acc;
}

// convert + transpose W_h / W_g levels 0,1 to tf32 bits [l][n][k]
__global__ void prep_cvt(const float* __restrict__ Wh,
                         const float* __restrict__ Wg) {
    int i = blockIdx.x * 256 + threadIdx.x;   // 0 .. 32767
    int l = i >> 14, rem = i & 16383, n = rem >> 7, k = rem & 127;
    int src = (l << 14) + k * 128 + n;
    g_Whc[i] = f2tf(Wh[src]);
    g_Wgc[i] = f2tf(Wg[src]);
}

// ============================================================================
// fused_level: per block 128 child rows = 8 parents (warp w <-> parent w).
// ============================================================================
__global__ void __launch_bounds__(256, 2)
fused_level(const float* __restrict__ xin, const int* __restrict__ tvec,
            const float* __restrict__ tapg, const unsigned* __restrict__ Wc,
            const float* __restrict__ biasg,
            const float* __restrict__ hin,
            const float* __restrict__ Ag, const float* __restrict__ Eg,
            const float* __restrict__ Weg,
            const unsigned* __restrict__ Wg, const float* __restrict__ bgg,
            float* __restrict__ pooled)
{
    extern __shared__ unsigned char smraw[];
    unsigned* h2s = (unsigned*)smraw;                       // [128][132]
    unsigned* Wks = h2s + 128 * H2_STRIDE;                  // [2][128][20]
    float* taps   = (float*)(Wks + 2 * WT_CH);              // [4][128]
    float* bgs    = taps + 4 * 128;                         // [128]
    float* biass  = bgs + 128;                              // [128]
    int*   ts     = (int*)(biass + 128);                    // [128]

    const int t = threadIdx.x;
    const int lane = t & 31, wid = t >> 5;
    const int warpM = wid >> 2, warpN = wid & 3;
    const int g = lane >> 2, tg = lane & 3;
    const size_t rowbase = (size_t)blockIdx.x * 128;

    if (t < 128) bgs[t] = bgg[t];

    float4 acc[4][4];
    float gg[2][2][2];   // [c8][k8][k4] gate values for this lane's parent

    if (xin) {
        if (t < 128) { biass[t] = biasg[t]; ts[t] = tvec[rowbase + t]; }
        taps[t] = tapg[t]; taps[t + 256] = tapg[t + 256];

        // preload full X tile into h2s (tf32 bits)
        loadTile(h2s, xin, rowbase, t);

        #pragma unroll
        for (int i = 0; i < 4; ++i)
            #pragma unroll
            for (int j = 0; j < 4; ++j) acc[i][j] = make_float4(0.f, 0.f, 0.f, 0.f);

        cpWc(Wks, Wc, 0, t); CP_COMMIT();
        #pragma unroll
        for (int it = 0; it < 8; ++it) {
            CP_WAIT0();
            __syncthreads();            // chunk it visible; tile visible at it==0
            if (it < 7) { cpWc(Wks + ((it + 1) & 1) * WT_CH, Wc, (it + 1) * 16, t); CP_COMMIT(); }
            mma_chunk_t(acc, h2s, it * 16, Wks + (it & 1) * WT_CH,
                        warpM, warpN, lane);
        }

        // gates (register-resident; no h2s access)
        {
            const size_t ebase = (size_t)blockIdx.x * 2048 + wid * 256;
            float we0 = Weg[0], we1 = Weg[1], we2 = Weg[2], we3 = Weg[3];
            float we4 = Weg[4], we5 = Weg[5], we6 = Weg[6], we7 = Weg[7];
            #pragma unroll
            for (int c8 = 0; c8 < 2; ++c8)
                #pragma unroll
                for (int k8 = 0; k8 < 2; ++k8)
                    #pragma unroll
                    for (int k4 = 0; k4 < 2; ++k4) {
                        int c = g + 8 * c8, k = tg + 4 * k4 + 8 * k8;
                        const float* e = Eg + (ebase + c * 16 + k) * 8;
                        float4 e0 = *(const float4*)(e);
                        float4 e1 = *(const float4*)(e + 4);
                        float s = e0.x * we0 + e0.y * we1 + e0.z * we2 + e0.w * we3
                                + e1.x * we4 + e1.y * we5 + e1.z * we6 + e1.w * we7;
                        gg[c8][k8][k4] = Ag[ebase + c * 16 + k] / (1.f + __expf(-s));
                    }
        }

        __syncthreads();   // all X fragment reads done before overwriting h2s

        // epilogue: fast tanh -> h2s (tf32 bits, packed STS.64)
        #pragma unroll
        for (int i = 0; i < 4; ++i) {
            int r0 = warpM * 64 + i * 16 + g, r1 = r0 + 8;
            const float* tap0 = taps + ts[r0] * 128;
            const float* tap1 = taps + ts[r1] * 128;
            #pragma unroll
            for (int j = 0; j < 4; ++j) {
                int c0 = warpN * 32 + j * 8 + tg * 2;
                uint2 w0, w1;
                w0.x = f2tf(fast_tanh(acc[i][j].x + biass[c0]     + tap0[c0]));
                w0.y = f2tf(fast_tanh(acc[i][j].y + biass[c0 + 1] + tap0[c0 + 1]));
                w1.x = f2tf(fast_tanh(acc[i][j].z + biass[c0]     + tap1[c0]));
                w1.y = f2tf(fast_tanh(acc[i][j].w + biass[c0 + 1] + tap1[c0 + 1]));
                *(uint2*)(h2s + r0 * H2_STRIDE + c0) = w0;
                *(uint2*)(h2s + r1 * H2_STRIDE + c0) = w1;
            }
        }
    } else {
        // load child hidden tile from global (cvt + STS.128)
        loadTile(h2s, hin, rowbase, t);
        {
            const size_t ebase = (size_t)blockIdx.x * 2048 + wid * 256;
            float we0 = Weg[0], we1 = Weg[1], we2 = Weg[2], we3 = Weg[3];
            float we4 = Weg[4], we5 = Weg[5], we6 = Weg[6], we7 = Weg[7];
            #pragma unroll
            for (int c8 = 0; c8 < 2; ++c8)
                #pragma unroll
                for (int k8 = 0; k8 < 2; ++k8)
                    #pragma unroll
                    for (int k4 = 0; k4 < 2; ++k4) {
                        int c = g + 8 * c8, k = tg + 4 * k4 + 8 * k8;
                        const float* e = Eg + (ebase + c * 16 + k) * 8;
                        float4 e0 = *(const float4*)(e);
                        float4 e1 = *(const float4*)(e + 4);
                        float s = e0.x * we0 + e0.y * we1 + e0.z * we2 + e0.w * we3
                                + e1.x * we4 + e1.y * we5 + e1.z * we6 + e1.w * we7;
                        gg[c8][k8][k4] = Ag[ebase + c * 16 + k] / (1.f + __expf(-s));
                    }
        }
    }
    __syncthreads();   // h2s (child hidden) complete

    // Phase C: per-parent mix M_p = G_p @ child_h_p  (warp wid = parent)
    {
        float4 macc[16];
        #pragma unroll
        for (int j = 0; j < 16; ++j) macc[j] = make_float4(0.f, 0.f, 0.f, 0.f);
        int p = wid;
        #pragma unroll
        for (int ks = 0; ks < 2; ++ks) {
            unsigned a[4];
            a[0] = f2tf(gg[0][ks][0]);
            a[1] = f2tf(gg[1][ks][0]);
            a[2] = f2tf(gg[0][ks][1]);
            a[3] = f2tf(gg[1][ks][1]);
            #pragma unroll
            for (int j = 0; j < 16; ++j) {
                unsigned b0 = h2s[(p * 16 + ks * 8 + tg) * H2_STRIDE + j * 8 + g];
                unsigned b1 = h2s[(p * 16 + ks * 8 + tg + 4) * H2_STRIDE + j * 8 + g];
                mma8(macc[j], a, b0, b1);
            }
        }
        __syncwarp();
        #pragma unroll
        for (int j = 0; j < 16; ++j) {
            int c0 = j * 8 + tg * 2;
            uint2 w0, w1;
            w0.x = f2tf(macc[j].x); w0.y = f2tf(macc[j].y);
            w1.x = f2tf(macc[j].z); w1.y = f2tf(macc[j].w);
            *(uint2*)(h2s + (p * 16 + g) * H2_STRIDE + c0)     = w0;
            *(uint2*)(h2s + (p * 16 + g + 8) * H2_STRIDE + c0) = w1;
        }
    }
    __syncthreads();

    // Phase D: Hc = relu(M @ Wg + bg); maxpool over each parent's 16 rows
    #pragma unroll
    for (int i = 0; i < 4; ++i)
        #pragma unroll
        for (int j = 0; j < 4; ++j) acc[i][j] = make_float4(0.f, 0.f, 0.f, 0.f);

    cpWc(Wks, Wg, 0, t); CP_COMMIT();
    #pragma unroll
    for (int it = 0; it < 8; ++it) {
        CP_WAIT0();
        __syncthreads();
        if (it < 7) { cpWc(Wks + ((it + 1) & 1) * WT_CH, Wg, (it + 1) * 16, t); CP_COMMIT(); }
        mma_chunk_t(acc, h2s, it * 16, Wks + (it & 1) * WT_CH,
                    warpM, warpN, lane);
    }

    // relu + 16-row maxpool (m-tile i == parent warpM*4+i exactly)
    #pragma unroll
    for (int i = 0; i < 4; ++i) {
        size_t parent = (size_t)blockIdx.x * 8 + warpM * 4 + i;
        #pragma unroll
        for (int j = 0; j < 4; ++j) {
            int c0 = warpN * 32 + j * 8 + tg * 2;
            float b0 = bgs[c0], b1 = bgs[c0 + 1];
            float v0 = fmaxf(fmaxf(acc[i][j].x + b0, acc[i][j].z + b0), 0.f);
            float v1 = fmaxf(fmaxf(acc[i][j].y + b1, acc[i][j].w + b1), 0.f);
            #pragma unroll
            for (int off = 16; off >= 4; off >>= 1) {
                v0 = fmaxf(v0, __shfl_xor_sync(0xffffffffu, v0, off));
                v1 = fmaxf(v1, __shfl_xor_sync(0xffffffffu, v1, off));
            }
            if (lane < 4)
                *(float2*)(pooled + parent * 128 + c0) = make_float2(v0, v1);
        }
    }
}

// ============================================================================
// gemm_tanh: out = tanh(A0 @ W0 + A1 @ W1 + bias + typerow[t]) , tf32 mma
// Per-segment whole-tile preload; transposed W via cp.async; LDSM fragments.
// ============================================================================
__global__ void __launch_bounds__(256, 2)
gemm_tanh(const float* __restrict__ A0g, const unsigned* __restrict__ W0,
          const float* __restrict__ A1g, const unsigned* __restrict__ W1,
          const float* __restrict__ biasg, const float* __restrict__ tapg,
          const int* __restrict__ tvec, float* __restrict__ out)
{
    extern __shared__ unsigned char smraw[];
    unsigned* Xt  = (unsigned*)smraw;                       // [128][132]
    unsigned* Wks = Xt + 128 * H2_STRIDE;                   // [2][128][20]
    float* taps   = (float*)(Wks + 2 * WT_CH);              // [4][128]
    float* biass  = taps + 4 * 128;                         // [128]
    int*   ts     = (int*)(biass + 128);                    // [128]

    const int t = threadIdx.x;
    const int lane = t & 31, wid = t >> 5;
    const int warpM = wid >> 2, warpN = wid & 3;
    const int g = lane >> 2, tg = lane & 3;
    const size_t rowbase = (size_t)blockIdx.x * 128;

    if (t < 128) { biass[t] = biasg[t]; ts[t] = tvec[rowbase + t]; }
    taps[t] = tapg[t]; taps[t + 256] = tapg[t + 256];

    const float* Aseg[2] = {A0g, A1g};
    const unsigned* Wseg[2] = {W0, W1};

    float4 acc[4][4];
    #pragma unroll
    for (int i = 0; i < 4; ++i)
        #pragma unroll
        for (int j = 0; j < 4; ++j) acc[i][j] = make_float4(0.f, 0.f, 0.f, 0.f);

    #pragma unroll
    for (int seg = 0; seg < 2; ++seg) {
        if (seg) __syncthreads();        // prior segment's tile reads done
        loadTile(Xt, Aseg[seg], rowbase, t);
        cpWc(Wks, Wseg[seg], 0, t); CP_COMMIT();
        #pragma unroll
        for (int it = 0; it < 8; ++it) {
            CP_WAIT0();
            __syncthreads();             // chunk + tile visible
            if (it < 7) { cpWc(Wks + ((it + 1) & 1) * WT_CH, Wseg[seg], (it + 1) * 16, t); CP_COMMIT(); }
            mma_chunk_t(acc, Xt, it * 16, Wks + (it & 1) * WT_CH,
                        warpM, warpN, lane);
        }
    }

    #pragma unroll
    for (int i = 0; i < 4; ++i) {
        int r0 = warpM * 64 + i * 16 + g, r1 = r0 + 8;
        const float* tap0 = taps + ts[r0] * 128;
        const float* tap1 = taps + ts[r1] * 128;
        #pragma unroll
        for (int j = 0; j < 4; ++j) {
            int c0 = warpN * 32 + j * 8 + tg * 2;
            float o0 = fast_tanh(acc[i][j].x + biass[c0]     + tap0[c0]);
            float o1 = fast_tanh(acc[i][j].y + biass[c0 + 1] + tap0[c0 + 1]);
            float o2 = fast_tanh(acc[i][j].z + biass[c0]     + tap1[c0]);
            float o3 = fast_tanh(acc[i][j].w + biass[c0 + 1] + tap1[c0 + 1]);
            *(float2*)(out + (rowbase + r0) * 128 + c0) = make_float2(o0, o1);
            *(float2*)(out + (rowbase + r1) * 128 + c0) = make_float2(o2, o3);
        }
    }
}

// ---------------- launch -----------------------------------------------
extern "C" void kernel_launch(void* const* d_in, const int* in_sizes, int n_in,
                              void* d_out, int out_size) {
    const float* x0   = (const float*)d_in[0];
    const float* x1   = (const float*)d_in[1];
    const float* x2   = (const float*)d_in[2];
    const int*   t0   = (const int*)  d_in[3];
    const int*   t1   = (const int*)  d_in[4];
    const int*   t2   = (const int*)  d_in[5];
    const float* A0   = (const float*)d_in[6];
    const float* A1   = (const float*)d_in[7];
    const float* E0   = (const float*)d_in[8];
    const float* E1   = (const float*)d_in[9];
    const float* W_fe = (const float*)d_in[10];
    const float* b_fe = (const float*)d_in[11];
    const float* W_x  = (const float*)d_in[12];
    const float* W_h  = (const float*)d_in[13];
    const float* W_e  = (const float*)d_in[14];
    const float* W_g  = (const float*)d_in[15];
    const float* b_g  = (const float*)d_in[16];
    const float* b_r  = (const float*)d_in[17];

    float *pooled, *h1, *bias;
    unsigned *Wc, *Whc, *Wgc;
    cudaGetSymbolAddress((void**)&pooled, g_pooled);
    cudaGetSymbolAddress((void**)&h1,     g_h1);
    cudaGetSymbolAddress((void**)&Wc,     g_Wc);
    cudaGetSymbolAddress((void**)&Whc,    g_Whc);
    cudaGetSymbolAddress((void**)&Wgc,    g_Wgc);
    cudaGetSymbolAddress((void**)&bias,   g_bias);

    const int SMEM_FL = (128 * H2_STRIDE + 2 * WT_CH) * 4
                      + (4 * 128 + 128 + 128 + 128) * 4;   // 91,648 B
    const int SMEM_GT = (128 * H2_STRIDE + 2 * WT_CH) * 4
                      + (4 * 128 + 128 + 128) * 4;         // 91,136 B
    cudaFuncSetAttribute(fused_level, cudaFuncAttributeMaxDynamicSharedMemorySize, SMEM_FL);
    cudaFuncSetAttribute(gemm_tanh,   cudaFuncAttributeMaxDynamicSharedMemorySize, SMEM_GT);

    // fold W_fe/b_fe into per-level weights; pre-convert + transpose weights
    prep_wc<<<3 * 128, 128>>>(W_fe, W_x);
    prep_bias<<<3, 128>>>(b_fe, W_x, b_r);
    prep_cvt<<<128, 256>>>(W_h, W_g);

    // level 2 + level 1 GNN fused: x2 -> h2 (smem) -> gate/mix -> relu GEMM -> pooled1
    fused_level<<<PB_N2 / 128, 256, SMEM_FL>>>(
        x2, t2, W_x + 2 * 132 * 128 + 128 * 128, Wc + 2 * 128 * 128, bias + 2 * 128,
        nullptr, A1, E1, W_e + 8, Wgc + 128 * 128, b_g + 128, pooled);

    // h1 = tanh(x1 @ Wc1 + pooled1 @ W_h1 + bias1 + typerow)
    gemm_tanh<<<PB_N1 / 128, 256, SMEM_GT>>>(
        x1, Wc + 128 * 128, pooled, Whc + 128 * 128,
        bias + 128, W_x + 132 * 128 + 128 * 128, t1, h1);

    // level 0 GNN fused (child hidden loaded from h1)
    fused_level<<<PB_N1 / 128, 256, SMEM_FL>>>(
        nullptr, nullptr, nullptr, nullptr, nullptr,
        h1, A0, E0, W_e, Wgc, b_g, pooled);

    // roots: h0 -> d_out
    gemm_tanh<<<PB_N0 / 128, 256, SMEM_GT>>>(
        x0, Wc, pooled, Whc,
        bias, W_x + 128 * 128, t0, (float*)d_out);
}